// round 2
// baseline (speedup 1.0000x reference)
#include <cuda_runtime.h>

#define HEADS   8
#define NTOK    4096
#define RANK    820        /* NTOK - int(NTOK*0.8) : # elements strictly below threshold */
#define ROWS    4
#define THREADS 256
#define CHUNK   512

// ---------------- device scratch (no allocations allowed) ----------------
__device__ float  g_qraw[32 * NTOK];      // [head*4+c][n]
__device__ float4 g_kT  [HEADS * NTOK];   // [head][n] -> (c0,c1,c2,c3)
__device__ float4 g_vT  [HEADS * NTOK];
__device__ float  g_qs[32];
__device__ float  g_ks[32];
__device__ float  g_pre[128 * 1024];      // attention output in proj layout [ch][pixel]

// ---------------- kernel 1: qkv = 1x1x1 group conv + depthwise 3x3 ----------------
// block = (o in 0..11, cd in 0..31); x layout: channel = t*32 + cd, pixel p = y*32+x
__global__ void prep_kernel(const float* __restrict__ x,
                            const float* __restrict__ wqkv,
                            const float* __restrict__ wdw) {
    __shared__ float sh[34][34];
    int o  = blockIdx.x;
    int cd = blockIdx.y;
    int tid = threadIdx.x;
    for (int i = tid; i < 34 * 34; i += THREADS) ((float*)sh)[i] = 0.f;
    __syncthreads();
    float w0 = wqkv[o * 4 + 0], w1 = wqkv[o * 4 + 1];
    float w2 = wqkv[o * 4 + 2], w3 = wqkv[o * 4 + 3];
    for (int p = tid; p < 1024; p += THREADS) {
        int y = p >> 5, xx = p & 31;
        float v = w0 * x[(0 * 32 + cd) * 1024 + p]
                + w1 * x[(1 * 32 + cd) * 1024 + p]
                + w2 * x[(2 * 32 + cd) * 1024 + p]
                + w3 * x[(3 * 32 + cd) * 1024 + p];
        sh[y + 1][xx + 1] = v;
    }
    __syncthreads();
    float k00 = wdw[o*9+0], k01 = wdw[o*9+1], k02 = wdw[o*9+2];
    float k10 = wdw[o*9+3], k11 = wdw[o*9+4], k12 = wdw[o*9+5];
    float k20 = wdw[o*9+6], k21 = wdw[o*9+7], k22 = wdw[o*9+8];
    int g = o >> 2, tt = o & 3;
    int head = cd >> 2, c = cd & 3;
    for (int p = tid; p < 1024; p += THREADS) {
        int y = p >> 5, xx = p & 31;
        float s = k00*sh[y  ][xx] + k01*sh[y  ][xx+1] + k02*sh[y  ][xx+2]
                + k10*sh[y+1][xx] + k11*sh[y+1][xx+1] + k12*sh[y+1][xx+2]
                + k20*sh[y+2][xx] + k21*sh[y+2][xx+1] + k22*sh[y+2][xx+2];
        int n = (p << 2) + tt;   // flat token index: t fastest
        if (g == 0)      g_qraw[cd * NTOK + n] = s;
        else if (g == 1) ((float*)g_kT)[(head * NTOK + n) * 4 + c] = s;
        else             ((float*)g_vT)[(head * NTOK + n) * 4 + c] = s;
    }
}

// ---------------- kernel 2: per-(head,c) L2 norms of q and k ----------------
__global__ void norm_kernel() {
    int i = blockIdx.x;   // 0..63 : [0,32)=q  [32,64)=k
    int tid = threadIdx.x;
    float s = 0.f;
    if (i < 32) {
        const float* q = g_qraw + i * NTOK;
        for (int n = tid; n < NTOK; n += THREADS) { float v = q[n]; s += v * v; }
    } else {
        int j = i - 32; int head = j >> 2, c = j & 3;
        const float* k = ((const float*)g_kT) + head * NTOK * 4 + c;
        for (int n = tid; n < NTOK; n += THREADS) { float v = k[n * 4]; s += v * v; }
    }
    __shared__ float red[8];
    for (int off = 16; off; off >>= 1) s += __shfl_down_sync(0xffffffffu, s, off);
    if ((tid & 31) == 0) red[tid >> 5] = s;
    __syncthreads();
    if (tid == 0) {
        float t = 0.f;
        for (int w = 0; w < 8; w++) t += red[w];
        float scale = 1.f / fmaxf(sqrtf(t), 1e-12f);
        if (i < 32) g_qs[i] = scale; else g_ks[i - 32] = scale;
    }
}

// ---------------- kernel 3: fused scores + exact top-k select + softmax + p@v ----------------
// 1 CTA = 4 consecutive rows of one head. Dyn smem:
//   sc[4][4096] (64KB) | buf[512] float4 (8KB) | hist[4][256] (4KB) | tail (~0.8KB)
#define SMEM_SC    (4 * NTOK * 4)
#define SMEM_BUF   (CHUNK * 16)
#define SMEM_HIST  (4 * 256 * 4)
#define SMEM_TAIL  (4*4 + 4*4 + 4*4 + 160*4 + 20*4)
#define SMEM_BYTES (SMEM_SC + SMEM_BUF + SMEM_HIST + SMEM_TAIL)

__device__ __forceinline__ unsigned ordkey(float f) {
    unsigned u = __float_as_uint(f);
    return (u & 0x80000000u) ? ~u : (u | 0x80000000u);
}

__global__ void __launch_bounds__(THREADS) attn_kernel(const float* __restrict__ temperature) {
    extern __shared__ char smem[];
    float*    sc   = (float*)smem;
    float4*   buf  = (float4*)(smem + SMEM_SC);
    unsigned* hist = (unsigned*)(smem + SMEM_SC + SMEM_BUF);
    char* tail = smem + SMEM_SC + SMEM_BUF + SMEM_HIST;
    float*    smaxr   = (float*)tail;                 // [4]
    unsigned* sprefix = (unsigned*)(smaxr + 4);       // [4]
    unsigned* starget = sprefix + 4;                  // [4]
    float*    sred    = (float*)(starget + 4);        // [160]
    float*    sfin    = sred + 160;                   // [20]

    int bx   = blockIdx.x;
    int head = bx >> 10;
    int n0   = (bx & 1023) << 2;
    int tid  = threadIdx.x;
    int lane = tid & 31, wid = tid >> 5;

    // fold q-norm * k-norm * temperature into per-row 4-coefficients
    float temp = temperature[head];
    float4 cf[ROWS];
    #pragma unroll
    for (int r = 0; r < ROWS; r++) {
        int n = n0 + r;
        float a0 = g_qraw[(head*4+0)*NTOK + n] * g_qs[head*4+0] * g_ks[head*4+0] * temp;
        float a1 = g_qraw[(head*4+1)*NTOK + n] * g_qs[head*4+1] * g_ks[head*4+1] * temp;
        float a2 = g_qraw[(head*4+2)*NTOK + n] * g_qs[head*4+2] * g_ks[head*4+2] * temp;
        float a3 = g_qraw[(head*4+3)*NTOK + n] * g_qs[head*4+3] * g_ks[head*4+3] * temp;
        cf[r] = make_float4(a0, a1, a2, a3);
    }

    // ---- pass 1: scores into shared, track row max ----
    float rmax[ROWS];
    #pragma unroll
    for (int r = 0; r < ROWS; r++) rmax[r] = -3.4e38f;
    const float4* kt = g_kT + head * NTOK;
    for (int base = 0; base < NTOK; base += CHUNK) {
        buf[tid]       = kt[base + tid];
        buf[tid + 256] = kt[base + tid + 256];
        __syncthreads();
        #pragma unroll
        for (int jj = 0; jj < 2; jj++) {
            int m = base + tid + jj * 256;
            float4 kv = buf[tid + jj * 256];
            #pragma unroll
            for (int r = 0; r < ROWS; r++) {
                float s = cf[r].x*kv.x + cf[r].y*kv.y + cf[r].z*kv.z + cf[r].w*kv.w;
                sc[r * NTOK + m] = s;
                rmax[r] = fmaxf(rmax[r], s);
            }
        }
        __syncthreads();
    }

    // block-reduce row maxima
    #pragma unroll
    for (int r = 0; r < ROWS; r++)
        for (int off = 16; off; off >>= 1)
            rmax[r] = fmaxf(rmax[r], __shfl_down_sync(0xffffffffu, rmax[r], off));
    if (lane == 0) {
        #pragma unroll
        for (int r = 0; r < ROWS; r++) sred[r * 8 + wid] = rmax[r];
    }
    __syncthreads();
    if (tid < ROWS) {
        float mx = sred[tid * 8];
        for (int w = 1; w < 8; w++) mx = fmaxf(mx, sred[tid * 8 + w]);
        smaxr[tid]   = mx;
        sprefix[tid] = 0u;
        starget[tid] = RANK;
    }
    __syncthreads();

    // ---- pass 2: exact radix select (4 rounds, 8-bit digits, 4 rows concurrently) ----
    for (int round = 0; round < 4; round++) {
        int shift = 24 - 8 * round;
        unsigned mask = round ? (0xFFFFFFFFu << (shift + 8)) : 0u;
        for (int i = tid; i < 4 * 256; i += THREADS) hist[i] = 0u;
        __syncthreads();
        unsigned pref[ROWS];
        #pragma unroll
        for (int r = 0; r < ROWS; r++) pref[r] = sprefix[r];
        for (int j = 0; j < 16; j++) {
            int m = tid + (j << 8);
            #pragma unroll
            for (int r = 0; r < ROWS; r++) {
                unsigned u = ordkey(sc[r * NTOK + m]);
                bool cand = ((u & mask) == pref[r]);
                unsigned digit = (u >> shift) & 255u;
                unsigned active = __ballot_sync(0xffffffffu, cand);
                if (cand) {
                    unsigned same = __match_any_sync(active, digit);
                    int leader = __ffs(same) - 1;
                    if (lane == leader)
                        atomicAdd(&hist[r * 256 + digit], __popc(same));
                }
            }
        }
        __syncthreads();
        if (wid < ROWS) {
            int r = wid;
            unsigned t = starget[r];
            unsigned loc[8], lsum = 0;
            #pragma unroll
            for (int i = 0; i < 8; i++) { loc[i] = hist[r * 256 + lane * 8 + i]; lsum += loc[i]; }
            unsigned run = lsum;
            #pragma unroll
            for (int d = 1; d < 32; d <<= 1) {
                unsigned v = __shfl_up_sync(0xffffffffu, run, d);
                if (lane >= d) run += v;
            }
            unsigned cum = run - lsum;   // exclusive prefix
            int foundBin = -1; unsigned cumBefore = 0;
            #pragma unroll
            for (int i = 0; i < 8; i++) {
                if (foundBin < 0 && cum <= t && cum + loc[i] > t) { foundBin = lane * 8 + i; cumBefore = cum; }
                cum += loc[i];
            }
            unsigned bal = __ballot_sync(0xffffffffu, foundBin >= 0);
            int src = __ffs(bal) - 1;
            int bin = __shfl_sync(0xffffffffu, foundBin, src);
            unsigned cb = __shfl_sync(0xffffffffu, cumBefore, src);
            if (lane == 0) { sprefix[r] = pref[r] | (((unsigned)bin) << shift); starget[r] = t - cb; }
        }
        __syncthreads();
    }

    // ---- pass 3: masked softmax + p@v, fused ----
    unsigned tkey[ROWS]; float mrow[ROWS];
    #pragma unroll
    for (int r = 0; r < ROWS; r++) { tkey[r] = sprefix[r]; mrow[r] = smaxr[r]; }
    float z[ROWS] = {0.f, 0.f, 0.f, 0.f};
    float4 acc[ROWS];
    #pragma unroll
    for (int r = 0; r < ROWS; r++) acc[r] = make_float4(0.f, 0.f, 0.f, 0.f);
    const float4* vt = g_vT + head * NTOK;
    for (int base = 0; base < NTOK; base += CHUNK) {
        __syncthreads();                 // previous chunk fully consumed
        buf[tid]       = vt[base + tid];
        buf[tid + 256] = vt[base + tid + 256];
        __syncthreads();
        #pragma unroll
        for (int jj = 0; jj < 2; jj++) {
            int m = base + tid + jj * 256;
            float4 vv = buf[tid + jj * 256];
            #pragma unroll
            for (int r = 0; r < ROWS; r++) {
                float f = sc[r * NTOK + m];
                if (ordkey(f) >= tkey[r]) {
                    float w = __expf(f - mrow[r]);
                    z[r] += w;
                    acc[r].x += w * vv.x; acc[r].y += w * vv.y;
                    acc[r].z += w * vv.z; acc[r].w += w * vv.w;
                }
            }
        }
    }

    // block-reduce 20 accumulators (z[4] + acc[4].xyzw)
    float vals[20];
    #pragma unroll
    for (int r = 0; r < ROWS; r++) {
        vals[r * 5 + 0] = z[r];
        vals[r * 5 + 1] = acc[r].x; vals[r * 5 + 2] = acc[r].y;
        vals[r * 5 + 3] = acc[r].z; vals[r * 5 + 4] = acc[r].w;
    }
    #pragma unroll
    for (int q = 0; q < 20; q++)
        for (int off = 16; off; off >>= 1)
            vals[q] += __shfl_down_sync(0xffffffffu, vals[q], off);
    if (lane == 0) {
        #pragma unroll
        for (int q = 0; q < 20; q++) sred[q * 8 + wid] = vals[q];
    }
    __syncthreads();
    if (tid < 20) {
        float s = 0.f;
        for (int w = 0; w < 8; w++) s += sred[tid * 8 + w];
        sfin[tid] = s;
    }
    __syncthreads();
    if (tid < 16) {
        int r = tid >> 2, c = tid & 3;
        float val = sfin[r * 5 + 1 + c] / sfin[r * 5 + 0];
        int n = n0 + r;
        int tt = n & 3, pixel = n >> 2;
        int ch = tt * 32 + head * 4 + c;     // output channel layout after transpose
        g_pre[ch * 1024 + pixel] = val;
    }
}

// ---------------- kernel 4: final 1x1 projection ----------------
__global__ void proj_kernel(const float* __restrict__ wproj, float* __restrict__ out) {
    int idx = blockIdx.x * THREADS + threadIdx.x;   // o*1024 + p
    int o = idx >> 10, p = idx & 1023;
    const float* w = wproj + o * 128;
    float s = 0.f;
    #pragma unroll 8
    for (int ch = 0; ch < 128; ch++) s += w[ch] * g_pre[ch * 1024 + p];
    out[idx] = s;
}

// ---------------- launch ----------------
extern "C" void kernel_launch(void* const* d_in, const int* in_sizes, int n_in,
                              void* d_out, int out_size) {
    (void)in_sizes; (void)n_in; (void)out_size;
    const float* x           = (const float*)d_in[0];
    const float* temperature = (const float*)d_in[1];
    const float* wqkv        = (const float*)d_in[2];
    const float* wdw         = (const float*)d_in[3];
    const float* wproj       = (const float*)d_in[4];
    float* out = (float*)d_out;

    cudaFuncSetAttribute(attn_kernel, cudaFuncAttributeMaxDynamicSharedMemorySize, SMEM_BYTES);

    prep_kernel<<<dim3(12, 32), THREADS>>>(x, wqkv, wdw);
    norm_kernel<<<64, THREADS>>>();
    attn_kernel<<<HEADS * (NTOK / ROWS), THREADS, SMEM_BYTES>>>(temperature);
    proj_kernel<<<(128 * 1024) / THREADS, THREADS>>>(wproj, out);
}

// round 4
// speedup vs baseline: 1.5960x; 1.5960x over previous
#include <cuda_runtime.h>

#define HEADS   8
#define NTOK    4096
#define RANK    820        /* NTOK - int(NTOK*0.8) : # elements strictly below threshold */
#define ROWS    4
#define THREADS 256
#define CAPR    192        /* max compacted borderline candidates per row */

// ---------------- device scratch (no allocations allowed) ----------------
__device__ float  g_qraw[32 * NTOK];      // [head*4+c][n]
__device__ float4 g_kT  [HEADS * NTOK];   // [head][n] -> (c0,c1,c2,c3)
__device__ float4 g_vT  [HEADS * NTOK];
__device__ float  g_qs[32];
__device__ float  g_ks[32];
__device__ float  g_pre[128 * 1024];      // attention output in proj layout [ch][pixel]

// ---------------- kernel 1: qkv = 1x1x1 group conv + depthwise 3x3 ----------------
__global__ void prep_kernel(const float* __restrict__ x,
                            const float* __restrict__ wqkv,
                            const float* __restrict__ wdw) {
    __shared__ float sh[34][34];
    int o  = blockIdx.x;
    int cd = blockIdx.y;
    int tid = threadIdx.x;
    for (int i = tid; i < 34 * 34; i += THREADS) ((float*)sh)[i] = 0.f;
    __syncthreads();
    float w0 = wqkv[o * 4 + 0], w1 = wqkv[o * 4 + 1];
    float w2 = wqkv[o * 4 + 2], w3 = wqkv[o * 4 + 3];
    for (int p = tid; p < 1024; p += THREADS) {
        int y = p >> 5, xx = p & 31;
        float v = w0 * x[(0 * 32 + cd) * 1024 + p]
                + w1 * x[(1 * 32 + cd) * 1024 + p]
                + w2 * x[(2 * 32 + cd) * 1024 + p]
                + w3 * x[(3 * 32 + cd) * 1024 + p];
        sh[y + 1][xx + 1] = v;
    }
    __syncthreads();
    float k00 = wdw[o*9+0], k01 = wdw[o*9+1], k02 = wdw[o*9+2];
    float k10 = wdw[o*9+3], k11 = wdw[o*9+4], k12 = wdw[o*9+5];
    float k20 = wdw[o*9+6], k21 = wdw[o*9+7], k22 = wdw[o*9+8];
    int g = o >> 2, tt = o & 3;
    int head = cd >> 2, c = cd & 3;
    for (int p = tid; p < 1024; p += THREADS) {
        int y = p >> 5, xx = p & 31;
        float s = k00*sh[y  ][xx] + k01*sh[y  ][xx+1] + k02*sh[y  ][xx+2]
                + k10*sh[y+1][xx] + k11*sh[y+1][xx+1] + k12*sh[y+1][xx+2]
                + k20*sh[y+2][xx] + k21*sh[y+2][xx+1] + k22*sh[y+2][xx+2];
        int n = (p << 2) + tt;   // flat token index: t fastest
        if (g == 0)      g_qraw[cd * NTOK + n] = s;
        else if (g == 1) ((float*)g_kT)[(head * NTOK + n) * 4 + c] = s;
        else             ((float*)g_vT)[(head * NTOK + n) * 4 + c] = s;
    }
}

// ---------------- kernel 2: per-(head,c) L2 norms of q and k ----------------
__global__ void norm_kernel() {
    int i = blockIdx.x;   // 0..63 : [0,32)=q  [32,64)=k
    int tid = threadIdx.x;
    float s = 0.f;
    if (i < 32) {
        const float* q = g_qraw + i * NTOK;
        for (int n = tid; n < NTOK; n += THREADS) { float v = q[n]; s += v * v; }
    } else {
        int j = i - 32; int head = j >> 2, c = j & 3;
        const float* k = ((const float*)g_kT) + head * NTOK * 4 + c;
        for (int n = tid; n < NTOK; n += THREADS) { float v = k[n * 4]; s += v * v; }
    }
    __shared__ float red[8];
    for (int off = 16; off; off >>= 1) s += __shfl_down_sync(0xffffffffu, s, off);
    if ((tid & 31) == 0) red[tid >> 5] = s;
    __syncthreads();
    if (tid == 0) {
        float t = 0.f;
        for (int w = 0; w < 8; w++) t += red[w];
        float scale = 1.f / fmaxf(sqrtf(t), 1e-12f);
        if (i < 32) g_qs[i] = scale; else g_ks[i - 32] = scale;
    }
}

// ---------------- kernel 3: fused scores + exact rank select + softmax + p@v ----------------
// smem: sc[4][4096] uint ordkeys (64KB) | buf[4][CAPR] (3KB) | control (~2KB)
#define SMEM_SC    (ROWS * NTOK * 4)
#define SMEM_BUF   (ROWS * CAPR * 4)
#define SMEM_CTRL  2048
#define SMEM_BYTES (SMEM_SC + SMEM_BUF + SMEM_CTRL)

__device__ __forceinline__ unsigned ordkey(float f) {
    unsigned u = __float_as_uint(f);
    return u ^ (0x80000000u | (unsigned)((int)u >> 31));
}
__device__ __forceinline__ float inv_ordkey(unsigned u) {
    return __uint_as_float(u ^ (0x80000000u | ~(unsigned)((int)u >> 31)));
}

__global__ void __launch_bounds__(THREADS) attn_kernel(const float* __restrict__ temperature) {
    extern __shared__ char smem[];
    unsigned* sc  = (unsigned*)smem;                       // ROWS*NTOK ordkeys
    unsigned* buf = (unsigned*)(smem + SMEM_SC);           // ROWS*CAPR
    char* ctrl = smem + SMEM_SC + SMEM_BUF;
    unsigned* cnt    = (unsigned*)ctrl;            // [4]  compaction counters
    unsigned* slo    = cnt + 4;                    // [4]
    unsigned* shi    = slo + 4;                    // [4]
    int*      sclo   = (int*)(shi + 4);            // [4]
    int*      schi   = sclo + 4;                   // [4]
    unsigned* sdone  = (unsigned*)(schi + 4);      // [4] 0=active 1=compact 2=exact
    unsigned* spiv   = sdone + 4;                  // [4]
    unsigned* stkey  = spiv + 4;                   // [4]
    float*    smaxf  = (float*)(stkey + 4);        // [4]
    unsigned* wred   = (unsigned*)(smaxf + 4);     // [8*8] warp partials
    float*    sred   = (float*)(wred + 64);        // [160]
    float*    sfin   = sred + 160;                 // [20]

    int bx   = blockIdx.x;
    int head = bx >> 10;
    int n0   = (bx & 1023) << 2;
    int tid  = threadIdx.x;
    int lane = tid & 31, wid = tid >> 5;

    // fold q-norm * k-norm * temperature into per-row coefficients
    float temp = temperature[head];
    float4 cf[ROWS];
    #pragma unroll
    for (int r = 0; r < ROWS; r++) {
        int n = n0 + r;
        float a0 = g_qraw[(head*4+0)*NTOK + n] * g_qs[head*4+0] * g_ks[head*4+0] * temp;
        float a1 = g_qraw[(head*4+1)*NTOK + n] * g_qs[head*4+1] * g_ks[head*4+1] * temp;
        float a2 = g_qraw[(head*4+2)*NTOK + n] * g_qs[head*4+2] * g_ks[head*4+2] * temp;
        float a3 = g_qraw[(head*4+3)*NTOK + n] * g_qs[head*4+3] * g_ks[head*4+3] * temp;
        cf[r] = make_float4(a0, a1, a2, a3);
    }

    // ---- pass 1: ordkeys into shared, per-row key min/max ----
    unsigned umax[ROWS], umin[ROWS];
    #pragma unroll
    for (int r = 0; r < ROWS; r++) { umax[r] = 0u; umin[r] = 0xFFFFFFFFu; }
    const float4* kt = g_kT + head * NTOK;
    #pragma unroll 4
    for (int j = 0; j < 16; j++) {
        int m = tid + (j << 8);
        float4 kv = __ldg(&kt[m]);
        #pragma unroll
        for (int r = 0; r < ROWS; r++) {
            float s = fmaf(cf[r].x, kv.x, fmaf(cf[r].y, kv.y, fmaf(cf[r].z, kv.z, cf[r].w * kv.w)));
            unsigned u = ordkey(s);
            sc[r * NTOK + m] = u;
            umax[r] = max(umax[r], u);
            umin[r] = min(umin[r], u);
        }
    }
    // warp reduce min/max
    #pragma unroll
    for (int r = 0; r < ROWS; r++) {
        for (int off = 16; off; off >>= 1) {
            umax[r] = max(umax[r], __shfl_down_sync(0xffffffffu, umax[r], off));
            umin[r] = min(umin[r], __shfl_down_sync(0xffffffffu, umin[r], off));
        }
    }
    if (lane == 0) {
        #pragma unroll
        for (int r = 0; r < ROWS; r++) {
            wred[wid * 8 + r]     = umax[r];
            wred[wid * 8 + 4 + r] = umin[r];
        }
    }
    __syncthreads();
    if (tid < 8) {
        unsigned v = wred[tid];
        if (tid < 4) { for (int w = 1; w < 8; w++) v = max(v, wred[w * 8 + tid]); }
        else         { for (int w = 1; w < 8; w++) v = min(v, wred[w * 8 + tid]); }
        if (tid < 4) {
            shi[tid] = v + 1; schi[tid] = NTOK;
            smaxf[tid] = inv_ordkey(v);
        } else {
            slo[tid - 4] = v; sclo[tid - 4] = 0;
        }
    }
    __syncthreads();
    if (tid < 4) {
        unsigned l = slo[tid], h = shi[tid];
        unsigned span = h - l;
        if (span <= 1) { stkey[tid] = l; sdone[tid] = 2u; }
        else           { sdone[tid] = 0u; spiv[tid] = l + (span >> 1); }
    }
    __syncthreads();

    // ---- pass 2: bracket search by count-below-pivot (pure ALU scans) ----
    for (int iter = 0; iter < 64; iter++) {
        unsigned d0 = sdone[0], d1 = sdone[1], d2 = sdone[2], d3 = sdone[3];
        if (d0 && d1 && d2 && d3) break;
        unsigned p0 = spiv[0], p1 = spiv[1], p2 = spiv[2], p3 = spiv[3];
        int c0 = 0, c1 = 0, c2 = 0, c3 = 0;
        #pragma unroll 4
        for (int j = 0; j < 16; j++) {
            int m = tid + (j << 8);
            if (!d0) c0 += (sc[0 * NTOK + m] < p0);
            if (!d1) c1 += (sc[1 * NTOK + m] < p1);
            if (!d2) c2 += (sc[2 * NTOK + m] < p2);
            if (!d3) c3 += (sc[3 * NTOK + m] < p3);
        }
        for (int off = 16; off; off >>= 1) {
            c0 += __shfl_down_sync(0xffffffffu, c0, off);
            c1 += __shfl_down_sync(0xffffffffu, c1, off);
            c2 += __shfl_down_sync(0xffffffffu, c2, off);
            c3 += __shfl_down_sync(0xffffffffu, c3, off);
        }
        if (lane == 0) {
            wred[wid * 4 + 0] = (unsigned)c0; wred[wid * 4 + 1] = (unsigned)c1;
            wred[wid * 4 + 2] = (unsigned)c2; wred[wid * 4 + 3] = (unsigned)c3;
        }
        __syncthreads();
        if (tid < 4 && !sdone[tid]) {
            int tot = 0;
            for (int w = 0; w < 8; w++) tot += (int)wred[w * 4 + tid];
            if (tot <= RANK) { slo[tid] = spiv[tid]; sclo[tid] = tot; }
            else             { shi[tid] = spiv[tid]; schi[tid] = tot; }
            unsigned l = slo[tid], h = shi[tid];
            unsigned span = h - l;
            int cc = schi[tid] - sclo[tid];
            if (span == 1)        { stkey[tid] = l; sdone[tid] = 2u; }
            else if (cc <= CAPR)  { sdone[tid] = 1u; }
            else {
                unsigned step;
                if (iter & 1) {
                    step = span >> 1;
                } else {
                    float fr = (float)(RANK + 1 - sclo[tid]) / (float)cc;
                    step = (unsigned)(fr * (float)span);
                    unsigned mn = span >> 4; if (!mn) mn = 1;
                    if (step < mn) step = mn;
                    if (step > span - mn) step = span - mn;
                }
                if (step == 0) step = 1;
                spiv[tid] = l + step;
            }
        }
        __syncthreads();
    }
    // safety net: unconverged row -> approximate threshold at bracket low end
    if (tid < 4 && sdone[tid] == 0u) { stkey[tid] = slo[tid]; sdone[tid] = 2u; }
    if (tid < 4) cnt[tid] = 0;
    __syncthreads();

    // ---- compaction of borderline candidates (rows with done==1) ----
    {
        unsigned lor[ROWS], spanr[ROWS], dr[ROWS];
        #pragma unroll
        for (int r = 0; r < ROWS; r++) { lor[r] = slo[r]; spanr[r] = shi[r] - slo[r]; dr[r] = sdone[r]; }
        unsigned lmask = (1u << lane) - 1u;
        #pragma unroll 2
        for (int j = 0; j < 16; j++) {
            int m = tid + (j << 8);
            #pragma unroll
            for (int r = 0; r < ROWS; r++) {
                if (dr[r] == 1u) {
                    unsigned u = sc[r * NTOK + m];
                    bool cand = (u - lor[r]) < spanr[r];
                    unsigned msk = __ballot_sync(0xffffffffu, cand);
                    if (cand) {
                        int rk = __popc(msk & lmask);
                        int leader = __ffs(msk) - 1;
                        unsigned base = 0;
                        if (lane == leader) base = atomicAdd(&cnt[r], (unsigned)__popc(msk));
                        base = __shfl_sync(msk, base, leader);     // mask = participating lanes only
                        unsigned pos = base + (unsigned)rk;
                        if (pos < CAPR) buf[r * CAPR + pos] = u;
                    }
                }
            }
        }
    }
    __syncthreads();

    // ---- exact all-pairs rank among <=CAPR candidates (2 warps per row) ----
    {
        int r = wid >> 1;
        if (sdone[r] == 1u) {
            int c   = (int)cnt[r];
            if (c > CAPR) c = CAPR;
            int tgt = RANK - sclo[r];
            int id  = ((wid & 1) << 5) + lane;    // 0..63
            const unsigned* lst = buf + r * CAPR;
            for (int i = id; i < c; i += 64) {
                unsigned u = lst[i];
                int lt = 0, le = 0;
                for (int k = 0; k < c; k++) {
                    unsigned w = lst[k];
                    lt += (w < u); le += (w <= u);
                }
                if (lt <= tgt && tgt < le) stkey[r] = u;
            }
        }
    }
    __syncthreads();

    // ---- pass 3: masked softmax + p@v ----
    unsigned tk[ROWS]; float mrow[ROWS];
    #pragma unroll
    for (int r = 0; r < ROWS; r++) { tk[r] = stkey[r]; mrow[r] = smaxf[r]; }
    float z[ROWS] = {0.f, 0.f, 0.f, 0.f};
    float4 acc[ROWS];
    #pragma unroll
    for (int r = 0; r < ROWS; r++) acc[r] = make_float4(0.f, 0.f, 0.f, 0.f);
    const float4* vt = g_vT + head * NTOK;
    #pragma unroll 2
    for (int j = 0; j < 16; j++) {
        int m = tid + (j << 8);
        float4 vv = __ldg(&vt[m]);
        #pragma unroll
        for (int r = 0; r < ROWS; r++) {
            unsigned u = sc[r * NTOK + m];
            if (u >= tk[r]) {
                float s = inv_ordkey(u);
                float w = __expf(s - mrow[r]);
                z[r] += w;
                acc[r].x += w * vv.x; acc[r].y += w * vv.y;
                acc[r].z += w * vv.z; acc[r].w += w * vv.w;
            }
        }
    }

    // block-reduce 20 accumulators
    float vals[20];
    #pragma unroll
    for (int r = 0; r < ROWS; r++) {
        vals[r * 5 + 0] = z[r];
        vals[r * 5 + 1] = acc[r].x; vals[r * 5 + 2] = acc[r].y;
        vals[r * 5 + 3] = acc[r].z; vals[r * 5 + 4] = acc[r].w;
    }
    #pragma unroll
    for (int q = 0; q < 20; q++)
        for (int off = 16; off; off >>= 1)
            vals[q] += __shfl_down_sync(0xffffffffu, vals[q], off);
    if (lane == 0) {
        #pragma unroll
        for (int q = 0; q < 20; q++) sred[q * 8 + wid] = vals[q];
    }
    __syncthreads();
    if (tid < 20) {
        float s = 0.f;
        for (int w = 0; w < 8; w++) s += sred[tid * 8 + w];
        sfin[tid] = s;
    }
    __syncthreads();
    if (tid < 16) {
        int r = tid >> 2, c = tid & 3;
        float val = sfin[r * 5 + 1 + c] / sfin[r * 5 + 0];
        int n = n0 + r;
        int tt = n & 3, pixel = n >> 2;
        int ch = tt * 32 + head * 4 + c;
        g_pre[ch * 1024 + pixel] = val;
    }
}

// ---------------- kernel 4: final 1x1 projection ----------------
__global__ void proj_kernel(const float* __restrict__ wproj, float* __restrict__ out) {
    int idx = blockIdx.x * THREADS + threadIdx.x;   // o*1024 + p
    int o = idx >> 10, p = idx & 1023;
    const float* w = wproj + o * 128;
    float s = 0.f;
    #pragma unroll 8
    for (int ch = 0; ch < 128; ch++) s += w[ch] * g_pre[ch * 1024 + p];
    out[idx] = s;
}

// ---------------- launch ----------------
extern "C" void kernel_launch(void* const* d_in, const int* in_sizes, int n_in,
                              void* d_out, int out_size) {
    (void)in_sizes; (void)n_in; (void)out_size;
    const float* x           = (const float*)d_in[0];
    const float* temperature = (const float*)d_in[1];
    const float* wqkv        = (const float*)d_in[2];
    const float* wdw         = (const float*)d_in[3];
    const float* wproj       = (const float*)d_in[4];
    float* out = (float*)d_out;

    cudaFuncSetAttribute(attn_kernel, cudaFuncAttributeMaxDynamicSharedMemorySize, SMEM_BYTES);

    prep_kernel<<<dim3(12, 32), THREADS>>>(x, wqkv, wdw);
    norm_kernel<<<64, THREADS>>>();
    attn_kernel<<<HEADS * (NTOK / ROWS), THREADS, SMEM_BYTES>>>(temperature);
    proj_kernel<<<(128 * 1024) / THREADS, THREADS>>>(wproj, out);
}

// round 5
// speedup vs baseline: 1.6729x; 1.0482x over previous
#include <cuda_runtime.h>

#define HEADS   8
#define NTOK    4096
#define RANK    820        /* # elements strictly below threshold */
#define ROWS    4
#define THREADS 256
#define CAPR    384        /* candidate buffer per row */
#define NREG    12         /* CAPR/32 */

// ---------------- device scratch ----------------
__device__ float  g_qraw[32 * NTOK];      // [head*4+c][n]
__device__ float4 g_kT  [HEADS * NTOK];   // [head][n] -> (c0,c1,c2,c3)
__device__ float4 g_vT  [HEADS * NTOK];
__device__ float  g_qs[32];
__device__ float  g_ks[32];
__device__ float  g_pre[128 * 1024];      // attention output in proj layout [ch][pixel]

// ---------------- kernel 1: qkv = 1x1x1 group conv + depthwise 3x3 ----------------
__global__ void prep_kernel(const float* __restrict__ x,
                            const float* __restrict__ wqkv,
                            const float* __restrict__ wdw) {
    __shared__ float sh[34][34];
    int o  = blockIdx.x;
    int cd = blockIdx.y;
    int tid = threadIdx.x;
    for (int i = tid; i < 34 * 34; i += THREADS) ((float*)sh)[i] = 0.f;
    __syncthreads();
    float w0 = wqkv[o * 4 + 0], w1 = wqkv[o * 4 + 1];
    float w2 = wqkv[o * 4 + 2], w3 = wqkv[o * 4 + 3];
    for (int p = tid; p < 1024; p += THREADS) {
        int y = p >> 5, xx = p & 31;
        float v = w0 * x[(0 * 32 + cd) * 1024 + p]
                + w1 * x[(1 * 32 + cd) * 1024 + p]
                + w2 * x[(2 * 32 + cd) * 1024 + p]
                + w3 * x[(3 * 32 + cd) * 1024 + p];
        sh[y + 1][xx + 1] = v;
    }
    __syncthreads();
    float k00 = wdw[o*9+0], k01 = wdw[o*9+1], k02 = wdw[o*9+2];
    float k10 = wdw[o*9+3], k11 = wdw[o*9+4], k12 = wdw[o*9+5];
    float k20 = wdw[o*9+6], k21 = wdw[o*9+7], k22 = wdw[o*9+8];
    int g = o >> 2, tt = o & 3;
    int head = cd >> 2, c = cd & 3;
    for (int p = tid; p < 1024; p += THREADS) {
        int y = p >> 5, xx = p & 31;
        float s = k00*sh[y  ][xx] + k01*sh[y  ][xx+1] + k02*sh[y  ][xx+2]
                + k10*sh[y+1][xx] + k11*sh[y+1][xx+1] + k12*sh[y+1][xx+2]
                + k20*sh[y+2][xx] + k21*sh[y+2][xx+1] + k22*sh[y+2][xx+2];
        int n = (p << 2) + tt;
        if (g == 0)      g_qraw[cd * NTOK + n] = s;
        else if (g == 1) ((float*)g_kT)[(head * NTOK + n) * 4 + c] = s;
        else             ((float*)g_vT)[(head * NTOK + n) * 4 + c] = s;
    }
}

// ---------------- kernel 2: per-(head,c) L2 norms of q and k ----------------
__global__ void norm_kernel() {
    int i = blockIdx.x;
    int tid = threadIdx.x;
    float s = 0.f;
    if (i < 32) {
        const float* q = g_qraw + i * NTOK;
        for (int n = tid; n < NTOK; n += THREADS) { float v = q[n]; s += v * v; }
    } else {
        int j = i - 32; int head = j >> 2, c = j & 3;
        const float* k = ((const float*)g_kT) + head * NTOK * 4 + c;
        for (int n = tid; n < NTOK; n += THREADS) { float v = k[n * 4]; s += v * v; }
    }
    __shared__ float red[8];
    for (int off = 16; off; off >>= 1) s += __shfl_down_sync(0xffffffffu, s, off);
    if ((tid & 31) == 0) red[tid >> 5] = s;
    __syncthreads();
    if (tid == 0) {
        float t = 0.f;
        for (int w = 0; w < 8; w++) t += red[w];
        float scale = 1.f / fmaxf(sqrtf(t), 1e-12f);
        if (i < 32) g_qs[i] = scale; else g_ks[i - 32] = scale;
    }
}

// ---------------- kernel 3 ----------------
#define SMEM_SC    (ROWS * NTOK * 4)
#define SMEM_BUF   (ROWS * CAPR * 4)
#define SMEM_CTRL  2048
#define SMEM_BYTES (SMEM_SC + SMEM_BUF + SMEM_CTRL)

__device__ __forceinline__ unsigned ordkey(float f) {
    unsigned u = __float_as_uint(f);
    return u ^ (0x80000000u | (unsigned)((int)u >> 31));
}
__device__ __forceinline__ float inv_ordkey(unsigned u) {
    return __uint_as_float(u ^ (0x80000000u | ~(unsigned)((int)u >> 31)));
}
__device__ __forceinline__ unsigned next_pivot(unsigned lo, unsigned hi, int clo, int chi, int useInterp) {
    unsigned span = hi - lo;
    unsigned step;
    if (!useInterp) step = span >> 1;
    else {
        float fr = (float)(RANK + 1 - clo) / (float)(chi - clo);
        step = (unsigned)(fr * (float)span);
        unsigned mn = span >> 4; if (!mn) mn = 1;
        if (step < mn) step = mn;
        if (step > span - mn) step = span - mn;
    }
    if (!step) step = 1;
    return lo + step;
}

__global__ void __launch_bounds__(THREADS, 3) attn_kernel(const float* __restrict__ temperature) {
    extern __shared__ char smem[];
    unsigned* sc  = (unsigned*)smem;
    unsigned* buf = (unsigned*)(smem + SMEM_SC);
    unsigned* C   = (unsigned*)(smem + SMEM_SC + SMEM_BUF);
    unsigned* cnt   = C;                 // [4]
    unsigned* state = C + 4;             // [4] 0=bisect 1=buffer-search 2=done 3=compact-pending
    unsigned* slo   = C + 8;             // [4]
    unsigned* shi   = C + 12;            // [4]
    int*      sclo  = (int*)(C + 16);    // [4]
    int*      schi  = (int*)(C + 20);    // [4]
    unsigned* spiv  = C + 24;            // [4]
    unsigned* stkey = C + 28;            // [4]
    unsigned* stgt  = C + 32;            // [4]
    unsigned* sukey = C + 36;            // [4]
    float*    smaxf = (float*)(C + 40);  // [4]
    unsigned* spv   = C + 44;            // [8]  two pivots per row
    int*      sany  = (int*)(C + 52);    // [1]
    unsigned* gcnt  = C + 53;            // [8]
    unsigned* wred  = C + 64;            // [96]
    float*    sred  = (float*)(C + 160); // [160]
    float*    sfin  = sred + 160;        // [20]

    int bx   = blockIdx.x;
    int head = bx >> 10;
    int n0   = (bx & 1023) << 2;
    int tid  = threadIdx.x;
    int lane = tid & 31, wid = tid >> 5;

    float temp = temperature[head];
    float4 cf[ROWS];
    #pragma unroll
    for (int r = 0; r < ROWS; r++) {
        int n = n0 + r;
        float a0 = g_qraw[(head*4+0)*NTOK + n] * g_qs[head*4+0] * g_ks[head*4+0] * temp;
        float a1 = g_qraw[(head*4+1)*NTOK + n] * g_qs[head*4+1] * g_ks[head*4+1] * temp;
        float a2 = g_qraw[(head*4+2)*NTOK + n] * g_qs[head*4+2] * g_ks[head*4+2] * temp;
        float a3 = g_qraw[(head*4+3)*NTOK + n] * g_qs[head*4+3] * g_ks[head*4+3] * temp;
        cf[r] = make_float4(a0, a1, a2, a3);
    }

    // ---- pass 1: scores -> ordkeys (vectorized STS), max + moments ----
    float fsum[ROWS] = {0,0,0,0}, fsq[ROWS] = {0,0,0,0};
    unsigned umax[ROWS] = {0,0,0,0};
    const float4* kt = g_kT + head * NTOK;
    #pragma unroll 1
    for (int jo = 0; jo < 4; jo++) {
        int mb = (tid << 4) + (jo << 2);
        float4 k0 = __ldg(&kt[mb+0]);
        float4 k1 = __ldg(&kt[mb+1]);
        float4 k2 = __ldg(&kt[mb+2]);
        float4 k3 = __ldg(&kt[mb+3]);
        #pragma unroll
        for (int r = 0; r < ROWS; r++) {
            float s0 = fmaf(cf[r].x,k0.x, fmaf(cf[r].y,k0.y, fmaf(cf[r].z,k0.z, cf[r].w*k0.w)));
            float s1 = fmaf(cf[r].x,k1.x, fmaf(cf[r].y,k1.y, fmaf(cf[r].z,k1.z, cf[r].w*k1.w)));
            float s2 = fmaf(cf[r].x,k2.x, fmaf(cf[r].y,k2.y, fmaf(cf[r].z,k2.z, cf[r].w*k2.w)));
            float s3 = fmaf(cf[r].x,k3.x, fmaf(cf[r].y,k3.y, fmaf(cf[r].z,k3.z, cf[r].w*k3.w)));
            fsum[r] += (s0 + s1) + (s2 + s3);
            fsq[r]  += fmaf(s0,s0, fmaf(s1,s1, fmaf(s2,s2, s3*s3)));
            uint4 uu;
            uu.x = ordkey(s0); uu.y = ordkey(s1); uu.z = ordkey(s2); uu.w = ordkey(s3);
            umax[r] = max(umax[r], max(max(uu.x,uu.y), max(uu.z,uu.w)));
            *(uint4*)(sc + r * NTOK + mb) = uu;
        }
    }
    #pragma unroll
    for (int r = 0; r < ROWS; r++) {
        umax[r] = __reduce_max_sync(0xffffffffu, umax[r]);
        for (int off = 16; off; off >>= 1) {
            fsum[r] += __shfl_xor_sync(0xffffffffu, fsum[r], off);
            fsq[r]  += __shfl_xor_sync(0xffffffffu, fsq[r],  off);
        }
    }
    if (lane == 0) {
        #pragma unroll
        for (int r = 0; r < ROWS; r++) {
            wred[wid*12 + r]     = umax[r];
            wred[wid*12 + 4 + r] = __float_as_uint(fsum[r]);
            wred[wid*12 + 8 + r] = __float_as_uint(fsq[r]);
        }
    }
    __syncthreads();
    if (tid < 12) {
        int r = tid & 3, kind = tid >> 2;
        if (kind == 0) {
            unsigned v = 0;
            for (int w = 0; w < 8; w++) v = max(v, wred[w*12 + r]);
            sukey[r] = v; smaxf[r] = inv_ordkey(v);
        } else {
            float s = 0.f;
            for (int w = 0; w < 8; w++) s += __uint_as_float(wred[w*12 + kind*4 + r]);
            sfin[tid] = s;
        }
    }
    __syncthreads();
    if (tid < 4) {
        float mean = sfin[4 + tid] * (1.f / 4096.f);
        float var  = sfin[8 + tid] * (1.f / 4096.f) - mean * mean;
        float sig  = sqrtf(fmaxf(var, 0.f));
        spv[tid*2 + 0] = ordkey(fmaf(-0.9741f, sig, mean));   // quantile 0.165
        spv[tid*2 + 1] = ordkey(fmaf(-0.7225f, sig, mean));   // quantile 0.235
        cnt[tid] = 0;
    }
    __syncthreads();

    // ---- scan: count below both pivots + speculative window compaction ----
    {
        unsigned c1[ROWS] = {0,0,0,0}, c5[ROWS] = {0,0,0,0};
        unsigned p1r[ROWS], p5r[ROWS];
        #pragma unroll
        for (int r = 0; r < ROWS; r++) { p1r[r] = spv[r*2]; p5r[r] = spv[r*2+1]; }
        unsigned lmask = (1u << lane) - 1u;
        #pragma unroll 1
        for (int jo = 0; jo < 4; jo++) {
            int mb = (tid << 4) + (jo << 2);
            #pragma unroll
            for (int r = 0; r < ROWS; r++) {
                uint4 uu = *(const uint4*)(sc + r * NTOK + mb);
                #pragma unroll
                for (int e = 0; e < 4; e++) {
                    unsigned u = (e==0)?uu.x:(e==1)?uu.y:(e==2)?uu.z:uu.w;
                    bool b1 = u < p1r[r], b5 = u < p5r[r];
                    c1[r] += b1; c5[r] += b5;
                    bool win = (!b1) && b5;
                    unsigned msk = __ballot_sync(0xffffffffu, win);
                    if (win) {
                        int rk = __popc(msk & lmask);
                        int ld = __ffs(msk) - 1;
                        unsigned bs = 0;
                        if (lane == ld) bs = atomicAdd(&cnt[r], (unsigned)__popc(msk));
                        bs = __shfl_sync(msk, bs, ld);
                        unsigned pos = bs + (unsigned)rk;
                        if (pos < CAPR) buf[r * CAPR + pos] = u;
                    }
                }
            }
        }
        #pragma unroll
        for (int r = 0; r < ROWS; r++) {
            c1[r] = __reduce_add_sync(0xffffffffu, c1[r]);
            c5[r] = __reduce_add_sync(0xffffffffu, c5[r]);
        }
        if (lane == 0) {
            #pragma unroll
            for (int r = 0; r < ROWS; r++) { wred[wid*8 + r] = c1[r]; wred[wid*8 + 4 + r] = c5[r]; }
        }
    }
    __syncthreads();
    if (tid < 8) {
        unsigned s = 0;
        for (int w = 0; w < 8; w++) s += wred[w*8 + tid];
        gcnt[tid] = s;
    }
    __syncthreads();

    // ---- classify rows ----
    if (tid < 4) {
        int c1v = (int)gcnt[tid], c5v = (int)gcnt[4 + tid];
        unsigned p1 = spv[tid*2], p5 = spv[tid*2 + 1];
        if (c1v <= RANK && RANK < c5v && (c5v - c1v) <= CAPR) {
            state[tid] = 1; slo[tid] = p1; shi[tid] = p5; stgt[tid] = (unsigned)(RANK - c1v);
        } else {
            unsigned lo, hi; int clo, chi;
            if (RANK < c1v)      { lo = 0u; hi = p1; clo = 0;   chi = c1v; }
            else if (RANK < c5v) { lo = p1; hi = p5; clo = c1v; chi = c5v; }
            else                 { lo = p5; hi = sukey[tid] + 1u; clo = c5v; chi = NTOK; }
            slo[tid] = lo; shi[tid] = hi; sclo[tid] = clo; schi[tid] = chi;
            if (hi - lo <= 1u)            { stkey[tid] = lo; state[tid] = 2; }
            else if (chi - clo <= CAPR)   { state[tid] = 3; }
            else { state[tid] = 0; spiv[tid] = next_pivot(lo, hi, clo, chi, 1); }
        }
    }

    // ---- fallback bisect loop (rare) ----
    for (int iter = 0; iter < 72; iter++) {
        __syncthreads();
        if (tid == 0)
            sany[0] = (state[0]==0) | (state[1]==0) | (state[2]==0) | (state[3]==0);
        __syncthreads();
        if (!sany[0]) break;
        unsigned pv[ROWS]; int act[ROWS];
        #pragma unroll
        for (int r = 0; r < ROWS; r++) { act[r] = (state[r] == 0); pv[r] = spiv[r]; }
        unsigned cr[ROWS] = {0,0,0,0};
        #pragma unroll 1
        for (int jo = 0; jo < 4; jo++) {
            int mb = (tid << 4) + (jo << 2);
            #pragma unroll
            for (int r = 0; r < ROWS; r++) {
                if (act[r]) {
                    uint4 uu = *(const uint4*)(sc + r * NTOK + mb);
                    cr[r] += (uu.x < pv[r]) + (uu.y < pv[r]) + (uu.z < pv[r]) + (uu.w < pv[r]);
                }
            }
        }
        #pragma unroll
        for (int r = 0; r < ROWS; r++) cr[r] = __reduce_add_sync(0xffffffffu, cr[r]);
        if (lane == 0) {
            #pragma unroll
            for (int r = 0; r < ROWS; r++) wred[wid*4 + r] = cr[r];
        }
        __syncthreads();
        if (tid < 4 && state[tid] == 0) {
            int tot = 0;
            for (int w = 0; w < 8; w++) tot += (int)wred[w*4 + tid];
            if (tot <= RANK) { slo[tid] = spiv[tid]; sclo[tid] = tot; }
            else             { shi[tid] = spiv[tid]; schi[tid] = tot; }
            unsigned lo = slo[tid], hi = shi[tid];
            int cc = schi[tid] - sclo[tid];
            if (hi - lo <= 1u)      { stkey[tid] = lo; state[tid] = 2; }
            else if (cc <= CAPR)    { state[tid] = 3; }
            else spiv[tid] = next_pivot(lo, hi, sclo[tid], schi[tid], !(iter & 1));
        }
    }
    __syncthreads();
    if (tid < 4) {
        if (state[tid] == 0) { stkey[tid] = slo[tid]; state[tid] = 2; } // safety
        if (state[tid] == 3) cnt[tid] = 0;
    }
    __syncthreads();

    // ---- fallback compaction (rows in state 3) ----
    {
        bool anyc = (state[0]==3) | (state[1]==3) | (state[2]==3) | (state[3]==3);
        if (anyc) {
            unsigned lor[ROWS], spn[ROWS]; int c3[ROWS];
            #pragma unroll
            for (int r = 0; r < ROWS; r++) {
                c3[r] = (state[r] == 3); lor[r] = slo[r]; spn[r] = shi[r] - slo[r];
            }
            unsigned lmask = (1u << lane) - 1u;
            #pragma unroll 1
            for (int jo = 0; jo < 4; jo++) {
                int mb = (tid << 4) + (jo << 2);
                #pragma unroll
                for (int r = 0; r < ROWS; r++) {
                    if (c3[r]) {
                        uint4 uu = *(const uint4*)(sc + r * NTOK + mb);
                        #pragma unroll
                        for (int e = 0; e < 4; e++) {
                            unsigned u = (e==0)?uu.x:(e==1)?uu.y:(e==2)?uu.z:uu.w;
                            bool win = (u - lor[r]) < spn[r];
                            unsigned msk = __ballot_sync(0xffffffffu, win);
                            if (win) {
                                int rk = __popc(msk & lmask);
                                int ld = __ffs(msk) - 1;
                                unsigned bs = 0;
                                if (lane == ld) bs = atomicAdd(&cnt[r], (unsigned)__popc(msk));
                                bs = __shfl_sync(msk, bs, ld);
                                unsigned pos = bs + (unsigned)rk;
                                if (pos < CAPR) buf[r * CAPR + pos] = u;
                            }
                        }
                    }
                }
            }
            __syncthreads();
            if (tid < 4 && state[tid] == 3) {
                stgt[tid] = (unsigned)(RANK - sclo[tid]);
                state[tid] = 1;
            }
            __syncthreads();
        }
    }

    // ---- warp-register bisect over candidate buffer (1 warp / row) ----
    if (wid < 4 && state[wid] == 1) {
        int c = (int)cnt[wid]; if (c > CAPR) c = CAPR;
        unsigned cand[NREG];
        #pragma unroll
        for (int i = 0; i < NREG; i++) {
            int idx = i * 32 + lane;
            cand[i] = (idx < c) ? buf[wid * CAPR + idx] : 0xFFFFFFFFu;
        }
        unsigned lo = slo[wid], hi = shi[wid], tgt = stgt[wid];
        while (hi - lo > 1u) {
            unsigned mid = lo + ((hi - lo) >> 1);
            unsigned cb = 0;
            #pragma unroll
            for (int i = 0; i < NREG; i++) cb += (cand[i] < mid);
            cb = __reduce_add_sync(0xffffffffu, cb);
            if (cb <= tgt) lo = mid; else hi = mid;
        }
        if (lane == 0) stkey[wid] = lo;
    }
    __syncthreads();

    // ---- pass 3: masked softmax + p@v ----
    unsigned tk[ROWS]; float mrow[ROWS];
    #pragma unroll
    for (int r = 0; r < ROWS; r++) { tk[r] = stkey[r]; mrow[r] = smaxf[r]; }
    float zz[ROWS] = {0.f, 0.f, 0.f, 0.f};
    float4 acc[ROWS];
    #pragma unroll
    for (int r = 0; r < ROWS; r++) acc[r] = make_float4(0.f, 0.f, 0.f, 0.f);
    const float4* vt = g_vT + head * NTOK;
    #pragma unroll 1
    for (int jo = 0; jo < 4; jo++) {
        int mb = (tid << 4) + (jo << 2);
        float4 v0 = __ldg(&vt[mb+0]);
        float4 v1 = __ldg(&vt[mb+1]);
        float4 v2 = __ldg(&vt[mb+2]);
        float4 v3 = __ldg(&vt[mb+3]);
        #pragma unroll
        for (int r = 0; r < ROWS; r++) {
            uint4 uu = *(const uint4*)(sc + r * NTOK + mb);
            {
                float w = (uu.x >= tk[r]) ? __expf(inv_ordkey(uu.x) - mrow[r]) : 0.f;
                zz[r] += w; acc[r].x += w*v0.x; acc[r].y += w*v0.y; acc[r].z += w*v0.z; acc[r].w += w*v0.w;
            }
            {
                float w = (uu.y >= tk[r]) ? __expf(inv_ordkey(uu.y) - mrow[r]) : 0.f;
                zz[r] += w; acc[r].x += w*v1.x; acc[r].y += w*v1.y; acc[r].z += w*v1.z; acc[r].w += w*v1.w;
            }
            {
                float w = (uu.z >= tk[r]) ? __expf(inv_ordkey(uu.z) - mrow[r]) : 0.f;
                zz[r] += w; acc[r].x += w*v2.x; acc[r].y += w*v2.y; acc[r].z += w*v2.z; acc[r].w += w*v2.w;
            }
            {
                float w = (uu.w >= tk[r]) ? __expf(inv_ordkey(uu.w) - mrow[r]) : 0.f;
                zz[r] += w; acc[r].x += w*v3.x; acc[r].y += w*v3.y; acc[r].z += w*v3.z; acc[r].w += w*v3.w;
            }
        }
    }

    // block-reduce 20 accumulators
    float vals[20];
    #pragma unroll
    for (int r = 0; r < ROWS; r++) {
        vals[r*5 + 0] = zz[r];
        vals[r*5 + 1] = acc[r].x; vals[r*5 + 2] = acc[r].y;
        vals[r*5 + 3] = acc[r].z; vals[r*5 + 4] = acc[r].w;
    }
    #pragma unroll
    for (int q = 0; q < 20; q++)
        for (int off = 16; off; off >>= 1)
            vals[q] += __shfl_down_sync(0xffffffffu, vals[q], off);
    if (lane == 0) {
        #pragma unroll
        for (int q = 0; q < 20; q++) sred[q*8 + wid] = vals[q];
    }
    __syncthreads();
    if (tid < 20) {
        float s = 0.f;
        for (int w = 0; w < 8; w++) s += sred[tid*8 + w];
        sfin[tid] = s;
    }
    __syncthreads();
    if (tid < 16) {
        int r = tid >> 2, c = tid & 3;
        float val = sfin[r*5 + 1 + c] / sfin[r*5 + 0];
        int n = n0 + r;
        int tt = n & 3, pixel = n >> 2;
        int ch = tt * 32 + head * 4 + c;
        g_pre[ch * 1024 + pixel] = val;
    }
}

// ---------------- kernel 4: final 1x1 projection ----------------
__global__ void proj_kernel(const float* __restrict__ wproj, float* __restrict__ out) {
    int idx = blockIdx.x * THREADS + threadIdx.x;
    int o = idx >> 10, p = idx & 1023;
    const float* w = wproj + o * 128;
    float s = 0.f;
    #pragma unroll 8
    for (int ch = 0; ch < 128; ch++) s += w[ch] * g_pre[ch * 1024 + p];
    out[idx] = s;
}

// ---------------- launch ----------------
extern "C" void kernel_launch(void* const* d_in, const int* in_sizes, int n_in,
                              void* d_out, int out_size) {
    (void)in_sizes; (void)n_in; (void)out_size;
    const float* x           = (const float*)d_in[0];
    const float* temperature = (const float*)d_in[1];
    const float* wqkv        = (const float*)d_in[2];
    const float* wdw         = (const float*)d_in[3];
    const float* wproj       = (const float*)d_in[4];
    float* out = (float*)d_out;

    cudaFuncSetAttribute(attn_kernel, cudaFuncAttributeMaxDynamicSharedMemorySize, SMEM_BYTES);

    prep_kernel<<<dim3(12, 32), THREADS>>>(x, wqkv, wdw);
    norm_kernel<<<64, THREADS>>>();
    attn_kernel<<<HEADS * (NTOK / ROWS), THREADS, SMEM_BYTES>>>(temperature);
    proj_kernel<<<(128 * 1024) / THREADS, THREADS>>>(wproj, out);
}

// round 6
// speedup vs baseline: 3.2340x; 1.9331x over previous
#include <cuda_runtime.h>

#define HEADS   8
#define NTOK    4096
#define RANK    820        /* # elements strictly below threshold */
#define ROWS    4
#define THREADS 256
#define CAPR    384        /* candidate buffer per row */
#define NREG    12         /* CAPR/32 */

// ---------------- device scratch ----------------
__device__ float  g_qraw[32 * NTOK];      // [head*4+c][n]
__device__ float4 g_kT  [HEADS * NTOK];   // [head][n] -> (c0,c1,c2,c3)
__device__ float4 g_vT  [HEADS * NTOK];
__device__ float  g_qs[32];
__device__ float  g_ks[32];
__device__ float  g_pre[128 * 1024];      // attention output in proj layout [ch][pixel]

// ---------------- kernel 1: qkv = 1x1x1 group conv + depthwise 3x3 ----------------
__global__ void prep_kernel(const float* __restrict__ x,
                            const float* __restrict__ wqkv,
                            const float* __restrict__ wdw) {
    __shared__ float sh[34][34];
    int o  = blockIdx.x;
    int cd = blockIdx.y;
    int tid = threadIdx.x;
    for (int i = tid; i < 34 * 34; i += THREADS) ((float*)sh)[i] = 0.f;
    __syncthreads();
    float w0 = wqkv[o * 4 + 0], w1 = wqkv[o * 4 + 1];
    float w2 = wqkv[o * 4 + 2], w3 = wqkv[o * 4 + 3];
    for (int p = tid; p < 1024; p += THREADS) {
        int y = p >> 5, xx = p & 31;
        float v = w0 * x[(0 * 32 + cd) * 1024 + p]
                + w1 * x[(1 * 32 + cd) * 1024 + p]
                + w2 * x[(2 * 32 + cd) * 1024 + p]
                + w3 * x[(3 * 32 + cd) * 1024 + p];
        sh[y + 1][xx + 1] = v;
    }
    __syncthreads();
    float k00 = wdw[o*9+0], k01 = wdw[o*9+1], k02 = wdw[o*9+2];
    float k10 = wdw[o*9+3], k11 = wdw[o*9+4], k12 = wdw[o*9+5];
    float k20 = wdw[o*9+6], k21 = wdw[o*9+7], k22 = wdw[o*9+8];
    int g = o >> 2, tt = o & 3;
    int head = cd >> 2, c = cd & 3;
    for (int p = tid; p < 1024; p += THREADS) {
        int y = p >> 5, xx = p & 31;
        float s = k00*sh[y  ][xx] + k01*sh[y  ][xx+1] + k02*sh[y  ][xx+2]
                + k10*sh[y+1][xx] + k11*sh[y+1][xx+1] + k12*sh[y+1][xx+2]
                + k20*sh[y+2][xx] + k21*sh[y+2][xx+1] + k22*sh[y+2][xx+2];
        int n = (p << 2) + tt;
        if (g == 0)      g_qraw[cd * NTOK + n] = s;
        else if (g == 1) ((float*)g_kT)[(head * NTOK + n) * 4 + c] = s;
        else             ((float*)g_vT)[(head * NTOK + n) * 4 + c] = s;
    }
}

// ---------------- kernel 2: per-(head,c) L2 norms of q and k ----------------
__global__ void norm_kernel() {
    int i = blockIdx.x;
    int tid = threadIdx.x;
    float s = 0.f;
    if (i < 32) {
        const float* q = g_qraw + i * NTOK;
        for (int n = tid; n < NTOK; n += THREADS) { float v = q[n]; s += v * v; }
    } else {
        int j = i - 32; int head = j >> 2, c = j & 3;
        const float* k = ((const float*)g_kT) + head * NTOK * 4 + c;
        for (int n = tid; n < NTOK; n += THREADS) { float v = k[n * 4]; s += v * v; }
    }
    __shared__ float red[8];
    for (int off = 16; off; off >>= 1) s += __shfl_down_sync(0xffffffffu, s, off);
    if ((tid & 31) == 0) red[tid >> 5] = s;
    __syncthreads();
    if (tid == 0) {
        float t = 0.f;
        for (int w = 0; w < 8; w++) t += red[w];
        float scale = 1.f / fmaxf(sqrtf(t), 1e-12f);
        if (i < 32) g_qs[i] = scale; else g_ks[i - 32] = scale;
    }
}

// ---------------- kernel 3 ----------------
#define SMEM_SC    (ROWS * NTOK * 4)
#define SMEM_BUF   (ROWS * CAPR * 4)
#define SMEM_CTRL  2048
#define SMEM_BYTES (SMEM_SC + SMEM_BUF + SMEM_CTRL)

__device__ __forceinline__ unsigned ordkey(float f) {
    unsigned u = __float_as_uint(f);
    return u ^ (0x80000000u | (unsigned)((int)u >> 31));
}
__device__ __forceinline__ float inv_ordkey(unsigned u) {
    return __uint_as_float(u ^ (0x80000000u | ~(unsigned)((int)u >> 31)));
}
__device__ __forceinline__ unsigned next_pivot(unsigned lo, unsigned hi, int clo, int chi, int useInterp) {
    unsigned span = hi - lo;
    unsigned step;
    if (!useInterp) step = span >> 1;
    else {
        float fr = (float)(RANK + 1 - clo) / (float)(chi - clo);
        step = (unsigned)(fr * (float)span);
        unsigned mn = span >> 4; if (!mn) mn = 1;
        if (step < mn) step = mn;
        if (step > span - mn) step = span - mn;
    }
    if (!step) step = 1;
    return lo + step;
}

__global__ void __launch_bounds__(THREADS, 3) attn_kernel(const float* __restrict__ temperature) {
    extern __shared__ char smem[];
    unsigned* sc  = (unsigned*)smem;
    unsigned* buf = (unsigned*)(smem + SMEM_SC);
    unsigned* C   = (unsigned*)(smem + SMEM_SC + SMEM_BUF);
    unsigned* cnt   = C;                 // [4]
    unsigned* state = C + 4;             // [4] 0=bisect 1=buffer-search 2=done 3=compact-pending
    unsigned* slo   = C + 8;             // [4]
    unsigned* shi   = C + 12;            // [4]
    int*      sclo  = (int*)(C + 16);    // [4]
    int*      schi  = (int*)(C + 20);    // [4]
    unsigned* spiv  = C + 24;            // [4]
    unsigned* stkey = C + 28;            // [4]
    unsigned* stgt  = C + 32;            // [4]
    unsigned* sukey = C + 36;            // [4]
    float*    smaxf = (float*)(C + 40);  // [4]
    unsigned* spv   = C + 44;            // [8]  two pivots per row
    int*      sany  = (int*)(C + 52);    // [1]
    unsigned* gcnt  = C + 53;            // [8]
    unsigned* wred  = C + 64;            // [96]
    float*    sred  = (float*)(C + 160); // [160]
    float*    sfin  = sred + 160;        // [20]

    int bx   = blockIdx.x;
    int head = bx >> 10;
    int n0   = (bx & 1023) << 2;
    int tid  = threadIdx.x;
    int lane = tid & 31, wid = tid >> 5;

    float temp = temperature[head];
    float4 cf[ROWS];
    #pragma unroll
    for (int r = 0; r < ROWS; r++) {
        int n = n0 + r;
        float a0 = g_qraw[(head*4+0)*NTOK + n] * g_qs[head*4+0] * g_ks[head*4+0] * temp;
        float a1 = g_qraw[(head*4+1)*NTOK + n] * g_qs[head*4+1] * g_ks[head*4+1] * temp;
        float a2 = g_qraw[(head*4+2)*NTOK + n] * g_qs[head*4+2] * g_ks[head*4+2] * temp;
        float a3 = g_qraw[(head*4+3)*NTOK + n] * g_qs[head*4+3] * g_ks[head*4+3] * temp;
        cf[r] = make_float4(a0, a1, a2, a3);
    }

    // ---- pass 1: scores -> ordkeys (conflict-free STS.128), max + moments ----
    // token block per (jo, thread): mb = jo*1024 + tid*4  (lanes at consecutive 16B)
    float fsum[ROWS] = {0,0,0,0}, fsq[ROWS] = {0,0,0,0};
    unsigned umax[ROWS] = {0,0,0,0};
    const float4* kt = g_kT + head * NTOK;
    #pragma unroll 1
    for (int jo = 0; jo < 4; jo++) {
        int mb = (jo << 10) + (tid << 2);
        float4 k0 = __ldg(&kt[mb+0]);
        float4 k1 = __ldg(&kt[mb+1]);
        float4 k2 = __ldg(&kt[mb+2]);
        float4 k3 = __ldg(&kt[mb+3]);
        #pragma unroll
        for (int r = 0; r < ROWS; r++) {
            float s0 = fmaf(cf[r].x,k0.x, fmaf(cf[r].y,k0.y, fmaf(cf[r].z,k0.z, cf[r].w*k0.w)));
            float s1 = fmaf(cf[r].x,k1.x, fmaf(cf[r].y,k1.y, fmaf(cf[r].z,k1.z, cf[r].w*k1.w)));
            float s2 = fmaf(cf[r].x,k2.x, fmaf(cf[r].y,k2.y, fmaf(cf[r].z,k2.z, cf[r].w*k2.w)));
            float s3 = fmaf(cf[r].x,k3.x, fmaf(cf[r].y,k3.y, fmaf(cf[r].z,k3.z, cf[r].w*k3.w)));
            fsum[r] += (s0 + s1) + (s2 + s3);
            fsq[r]  += fmaf(s0,s0, fmaf(s1,s1, fmaf(s2,s2, s3*s3)));
            uint4 uu;
            uu.x = ordkey(s0); uu.y = ordkey(s1); uu.z = ordkey(s2); uu.w = ordkey(s3);
            umax[r] = max(umax[r], max(max(uu.x,uu.y), max(uu.z,uu.w)));
            *(uint4*)(sc + r * NTOK + mb) = uu;
        }
    }
    #pragma unroll
    for (int r = 0; r < ROWS; r++) {
        umax[r] = __reduce_max_sync(0xffffffffu, umax[r]);
        for (int off = 16; off; off >>= 1) {
            fsum[r] += __shfl_xor_sync(0xffffffffu, fsum[r], off);
            fsq[r]  += __shfl_xor_sync(0xffffffffu, fsq[r],  off);
        }
    }
    if (lane == 0) {
        #pragma unroll
        for (int r = 0; r < ROWS; r++) {
            wred[wid*12 + r]     = umax[r];
            wred[wid*12 + 4 + r] = __float_as_uint(fsum[r]);
            wred[wid*12 + 8 + r] = __float_as_uint(fsq[r]);
        }
    }
    __syncthreads();
    if (tid < 12) {
        int r = tid & 3, kind = tid >> 2;
        if (kind == 0) {
            unsigned v = 0;
            for (int w = 0; w < 8; w++) v = max(v, wred[w*12 + r]);
            sukey[r] = v; smaxf[r] = inv_ordkey(v);
        } else {
            float s = 0.f;
            for (int w = 0; w < 8; w++) s += __uint_as_float(wred[w*12 + kind*4 + r]);
            sfin[tid] = s;
        }
    }
    __syncthreads();
    if (tid < 4) {
        float mean = sfin[4 + tid] * (1.f / 4096.f);
        float var  = sfin[8 + tid] * (1.f / 4096.f) - mean * mean;
        float sig  = sqrtf(fmaxf(var, 0.f));
        spv[tid*2 + 0] = ordkey(fmaf(-0.9741f, sig, mean));   // quantile 0.165
        spv[tid*2 + 1] = ordkey(fmaf(-0.7225f, sig, mean));   // quantile 0.235
        cnt[tid] = 0;
    }
    __syncthreads();

    // ---- scan: count below both pivots + speculative window compaction ----
    {
        unsigned c1[ROWS] = {0,0,0,0}, c5[ROWS] = {0,0,0,0};
        unsigned p1r[ROWS], p5r[ROWS];
        #pragma unroll
        for (int r = 0; r < ROWS; r++) { p1r[r] = spv[r*2]; p5r[r] = spv[r*2+1]; }
        #pragma unroll 1
        for (int jo = 0; jo < 4; jo++) {
            int mb = (jo << 10) + (tid << 2);
            #pragma unroll
            for (int r = 0; r < ROWS; r++) {
                uint4 uu = *(const uint4*)(sc + r * NTOK + mb);
                unsigned p1 = p1r[r], p5 = p5r[r], w = p5 - p1;
                int b1x = (uu.x < p1), b1y = (uu.y < p1), b1z = (uu.z < p1), b1w = (uu.w < p1);
                int wx = ((uu.x - p1) < w), wy = ((uu.y - p1) < w);
                int wz = ((uu.z - p1) < w), ww = ((uu.w - p1) < w);
                c1[r] += b1x + b1y + b1z + b1w;
                c5[r] += (b1x + b1y + b1z + b1w) + (wx + wy + wz + ww);
                int nc = wx + wy + wz + ww;
                if (nc) {
                    unsigned bs = atomicAdd(&cnt[r], (unsigned)nc);
                    if (bs + (unsigned)nc <= CAPR) {
                        unsigned* dst = buf + r * CAPR + bs;
                        if (wx) *dst++ = uu.x;
                        if (wy) *dst++ = uu.y;
                        if (wz) *dst++ = uu.z;
                        if (ww) *dst++ = uu.w;
                    }
                }
            }
        }
        #pragma unroll
        for (int r = 0; r < ROWS; r++) {
            c1[r] = __reduce_add_sync(0xffffffffu, c1[r]);
            c5[r] = __reduce_add_sync(0xffffffffu, c5[r]);
        }
        if (lane == 0) {
            #pragma unroll
            for (int r = 0; r < ROWS; r++) { wred[wid*8 + r] = c1[r]; wred[wid*8 + 4 + r] = c5[r]; }
        }
    }
    __syncthreads();
    if (tid < 8) {
        unsigned s = 0;
        for (int w = 0; w < 8; w++) s += wred[w*8 + tid];
        gcnt[tid] = s;
    }
    __syncthreads();

    // ---- classify rows ----
    if (tid < 4) {
        int c1v = (int)gcnt[tid], c5v = (int)gcnt[4 + tid];
        unsigned p1 = spv[tid*2], p5 = spv[tid*2 + 1];
        if (c1v <= RANK && RANK < c5v && (c5v - c1v) <= CAPR) {
            state[tid] = 1; slo[tid] = p1; shi[tid] = p5; stgt[tid] = (unsigned)(RANK - c1v);
        } else {
            unsigned lo, hi; int clo, chi;
            if (RANK < c1v)      { lo = 0u; hi = p1; clo = 0;   chi = c1v; }
            else if (RANK < c5v) { lo = p1; hi = p5; clo = c1v; chi = c5v; }
            else                 { lo = p5; hi = sukey[tid] + 1u; clo = c5v; chi = NTOK; }
            slo[tid] = lo; shi[tid] = hi; sclo[tid] = clo; schi[tid] = chi;
            if (hi - lo <= 1u)            { stkey[tid] = lo; state[tid] = 2; }
            else if (chi - clo <= CAPR)   { state[tid] = 3; }
            else { state[tid] = 0; spiv[tid] = next_pivot(lo, hi, clo, chi, 1); }
        }
    }

    // ---- fallback bisect loop (rare) ----
    for (int iter = 0; iter < 72; iter++) {
        __syncthreads();
        if (tid == 0)
            sany[0] = (state[0]==0) | (state[1]==0) | (state[2]==0) | (state[3]==0);
        __syncthreads();
        if (!sany[0]) break;
        unsigned pv[ROWS]; int act[ROWS];
        #pragma unroll
        for (int r = 0; r < ROWS; r++) { act[r] = (state[r] == 0); pv[r] = spiv[r]; }
        unsigned cr[ROWS] = {0,0,0,0};
        #pragma unroll 1
        for (int jo = 0; jo < 4; jo++) {
            int mb = (jo << 10) + (tid << 2);
            #pragma unroll
            for (int r = 0; r < ROWS; r++) {
                if (act[r]) {
                    uint4 uu = *(const uint4*)(sc + r * NTOK + mb);
                    cr[r] += (uu.x < pv[r]) + (uu.y < pv[r]) + (uu.z < pv[r]) + (uu.w < pv[r]);
                }
            }
        }
        #pragma unroll
        for (int r = 0; r < ROWS; r++) cr[r] = __reduce_add_sync(0xffffffffu, cr[r]);
        if (lane == 0) {
            #pragma unroll
            for (int r = 0; r < ROWS; r++) wred[wid*4 + r] = cr[r];
        }
        __syncthreads();
        if (tid < 4 && state[tid] == 0) {
            int tot = 0;
            for (int w = 0; w < 8; w++) tot += (int)wred[w*4 + tid];
            if (tot <= RANK) { slo[tid] = spiv[tid]; sclo[tid] = tot; }
            else             { shi[tid] = spiv[tid]; schi[tid] = tot; }
            unsigned lo = slo[tid], hi = shi[tid];
            int cc = schi[tid] - sclo[tid];
            if (hi - lo <= 1u)      { stkey[tid] = lo; state[tid] = 2; }
            else if (cc <= CAPR)    { state[tid] = 3; }
            else spiv[tid] = next_pivot(lo, hi, sclo[tid], schi[tid], !(iter & 1));
        }
    }
    __syncthreads();
    if (tid < 4) {
        if (state[tid] == 0) { stkey[tid] = slo[tid]; state[tid] = 2; } // safety
        if (state[tid] == 3) cnt[tid] = 0;
    }
    __syncthreads();

    // ---- fallback compaction (rows in state 3) ----
    {
        bool anyc = (state[0]==3) | (state[1]==3) | (state[2]==3) | (state[3]==3);
        if (anyc) {
            unsigned lor[ROWS], spn[ROWS]; int c3[ROWS];
            #pragma unroll
            for (int r = 0; r < ROWS; r++) {
                c3[r] = (state[r] == 3); lor[r] = slo[r]; spn[r] = shi[r] - slo[r];
            }
            #pragma unroll 1
            for (int jo = 0; jo < 4; jo++) {
                int mb = (jo << 10) + (tid << 2);
                #pragma unroll
                for (int r = 0; r < ROWS; r++) {
                    if (c3[r]) {
                        uint4 uu = *(const uint4*)(sc + r * NTOK + mb);
                        int wx = ((uu.x - lor[r]) < spn[r]);
                        int wy = ((uu.y - lor[r]) < spn[r]);
                        int wz = ((uu.z - lor[r]) < spn[r]);
                        int ww = ((uu.w - lor[r]) < spn[r]);
                        int nc = wx + wy + wz + ww;
                        if (nc) {
                            unsigned bs = atomicAdd(&cnt[r], (unsigned)nc);
                            if (bs + (unsigned)nc <= CAPR) {
                                unsigned* dst = buf + r * CAPR + bs;
                                if (wx) *dst++ = uu.x;
                                if (wy) *dst++ = uu.y;
                                if (wz) *dst++ = uu.z;
                                if (ww) *dst++ = uu.w;
                            }
                        }
                    }
                }
            }
            __syncthreads();
            if (tid < 4 && state[tid] == 3) {
                stgt[tid] = (unsigned)(RANK - sclo[tid]);
                state[tid] = 1;
            }
            __syncthreads();
        }
    }

    // ---- warp-register bisect over candidate buffer (1 warp / row) ----
    if (wid < 4 && state[wid] == 1) {
        int c = (int)cnt[wid]; if (c > CAPR) c = CAPR;
        unsigned cand[NREG];
        #pragma unroll
        for (int i = 0; i < NREG; i++) {
            int idx = i * 32 + lane;
            cand[i] = (idx < c) ? buf[wid * CAPR + idx] : 0xFFFFFFFFu;
        }
        unsigned lo = slo[wid], hi = shi[wid], tgt = stgt[wid];
        while (hi - lo > 1u) {
            unsigned mid = lo + ((hi - lo) >> 1);
            unsigned cb = 0;
            #pragma unroll
            for (int i = 0; i < NREG; i++) cb += (cand[i] < mid);
            cb = __reduce_add_sync(0xffffffffu, cb);
            if (cb <= tgt) lo = mid; else hi = mid;
        }
        if (lane == 0) stkey[wid] = lo;
    }
    __syncthreads();

    // ---- pass 3: masked softmax + p@v ----
    unsigned tk[ROWS]; float mrow[ROWS];
    #pragma unroll
    for (int r = 0; r < ROWS; r++) { tk[r] = stkey[r]; mrow[r] = smaxf[r]; }
    float zz[ROWS] = {0.f, 0.f, 0.f, 0.f};
    float4 acc[ROWS];
    #pragma unroll
    for (int r = 0; r < ROWS; r++) acc[r] = make_float4(0.f, 0.f, 0.f, 0.f);
    const float4* vt = g_vT + head * NTOK;
    #pragma unroll 1
    for (int jo = 0; jo < 4; jo++) {
        int mb = (jo << 10) + (tid << 2);
        float4 v0 = __ldg(&vt[mb+0]);
        float4 v1 = __ldg(&vt[mb+1]);
        float4 v2 = __ldg(&vt[mb+2]);
        float4 v3 = __ldg(&vt[mb+3]);
        #pragma unroll
        for (int r = 0; r < ROWS; r++) {
            uint4 uu = *(const uint4*)(sc + r * NTOK + mb);
            {
                float w = (uu.x >= tk[r]) ? __expf(inv_ordkey(uu.x) - mrow[r]) : 0.f;
                zz[r] += w; acc[r].x += w*v0.x; acc[r].y += w*v0.y; acc[r].z += w*v0.z; acc[r].w += w*v0.w;
            }
            {
                float w = (uu.y >= tk[r]) ? __expf(inv_ordkey(uu.y) - mrow[r]) : 0.f;
                zz[r] += w; acc[r].x += w*v1.x; acc[r].y += w*v1.y; acc[r].z += w*v1.z; acc[r].w += w*v1.w;
            }
            {
                float w = (uu.z >= tk[r]) ? __expf(inv_ordkey(uu.z) - mrow[r]) : 0.f;
                zz[r] += w; acc[r].x += w*v2.x; acc[r].y += w*v2.y; acc[r].z += w*v2.z; acc[r].w += w*v2.w;
            }
            {
                float w = (uu.w >= tk[r]) ? __expf(inv_ordkey(uu.w) - mrow[r]) : 0.f;
                zz[r] += w; acc[r].x += w*v3.x; acc[r].y += w*v3.y; acc[r].z += w*v3.z; acc[r].w += w*v3.w;
            }
        }
    }

    // block-reduce 20 accumulators
    float vals[20];
    #pragma unroll
    for (int r = 0; r < ROWS; r++) {
        vals[r*5 + 0] = zz[r];
        vals[r*5 + 1] = acc[r].x; vals[r*5 + 2] = acc[r].y;
        vals[r*5 + 3] = acc[r].z; vals[r*5 + 4] = acc[r].w;
    }
    #pragma unroll
    for (int q = 0; q < 20; q++)
        for (int off = 16; off; off >>= 1)
            vals[q] += __shfl_down_sync(0xffffffffu, vals[q], off);
    if (lane == 0) {
        #pragma unroll
        for (int q = 0; q < 20; q++) sred[q*8 + wid] = vals[q];
    }
    __syncthreads();
    if (tid < 20) {
        float s = 0.f;
        for (int w = 0; w < 8; w++) s += sred[tid*8 + w];
        sfin[tid] = s;
    }
    __syncthreads();
    if (tid < 16) {
        int r = tid >> 2, c = tid & 3;
        float val = sfin[r*5 + 1 + c] / sfin[r*5 + 0];
        int n = n0 + r;
        int tt = n & 3, pixel = n >> 2;
        int ch = tt * 32 + head * 4 + c;
        g_pre[ch * 1024 + pixel] = val;
    }
}

// ---------------- kernel 4: final 1x1 projection ----------------
__global__ void proj_kernel(const float* __restrict__ wproj, float* __restrict__ out) {
    int idx = blockIdx.x * THREADS + threadIdx.x;
    int o = idx >> 10, p = idx & 1023;
    const float* w = wproj + o * 128;
    float s = 0.f;
    #pragma unroll 8
    for (int ch = 0; ch < 128; ch++) s += w[ch] * g_pre[ch * 1024 + p];
    out[idx] = s;
}

// ---------------- launch ----------------
extern "C" void kernel_launch(void* const* d_in, const int* in_sizes, int n_in,
                              void* d_out, int out_size) {
    (void)in_sizes; (void)n_in; (void)out_size;
    const float* x           = (const float*)d_in[0];
    const float* temperature = (const float*)d_in[1];
    const float* wqkv        = (const float*)d_in[2];
    const float* wdw         = (const float*)d_in[3];
    const float* wproj       = (const float*)d_in[4];
    float* out = (float*)d_out;

    cudaFuncSetAttribute(attn_kernel, cudaFuncAttributeMaxDynamicSharedMemorySize, SMEM_BYTES);

    prep_kernel<<<dim3(12, 32), THREADS>>>(x, wqkv, wdw);
    norm_kernel<<<64, THREADS>>>();
    attn_kernel<<<HEADS * (NTOK / ROWS), THREADS, SMEM_BYTES>>>(temperature);
    proj_kernel<<<(128 * 1024) / THREADS, THREADS>>>(wproj, out);
}